// round 11
// baseline (speedup 1.0000x reference)
#include <cuda_runtime.h>
#include <cuda_bf16.h>

#define B_    32
#define PRE_  2048
#define POST_ 2048
#define KSPL  16

typedef unsigned int u32;

// ---- static device scratch ---------------------------------------------------
__device__ float g_part[KSPL * B_ * POST_];                   // fwd split-K partials
__device__ __align__(16) __nv_bfloat16 g_Apack[POST_ * 128];  // dw A operand (K-major)
__device__ __align__(16) __nv_bfloat16 g_Bpack[PRE_  * 128];  // dw B operand (K-major)

struct alignas(8) BV4 { __nv_bfloat16 v[4]; };

// ---- helpers -----------------------------------------------------------------
__device__ __forceinline__ u32 smem_u32(const void* p) {
    u32 a;
    asm("{ .reg .u64 t; cvta.to.shared.u64 t, %1; cvt.u32.u64 %0, t; }" : "=r"(a) : "l"(p));
    return a;
}
__device__ __forceinline__ void mma16816(float* d, const u32* a, const u32* b) {
    asm volatile(
        "mma.sync.aligned.m16n8k16.row.col.f32.bf16.bf16.f32 "
        "{%0,%1,%2,%3}, {%4,%5,%6,%7}, {%8,%9}, {%0,%1,%2,%3};"
        : "+f"(d[0]), "+f"(d[1]), "+f"(d[2]), "+f"(d[3])
        : "r"(a[0]), "r"(a[1]), "r"(a[2]), "r"(a[3]), "r"(b[0]), "r"(b[1]));
}
__device__ __forceinline__ u32 pack_bf2(__nv_bfloat16 a, __nv_bfloat16 b) {
    __nv_bfloat162 t = __halves2bfloat162(a, b);
    return *reinterpret_cast<u32*>(&t);
}
__device__ __forceinline__ void split3(float w, __nv_bfloat16& h,
                                       __nv_bfloat16& m, __nv_bfloat16& l) {
    h = __float2bfloat16(w);
    float r1 = w - __bfloat162float(h);
    m = __float2bfloat16(r1);
    l = __float2bfloat16(r1 - __bfloat162float(m));
}
#define CP_ASYNC16(dst, src) \
    asm volatile("cp.async.cg.shared.global [%0], [%1], 16;" :: "r"(dst), "l"(src) : "memory")
#define CP_COMMIT()  asm volatile("cp.async.commit_group;" ::: "memory")
#define CP_WAIT(n)   asm volatile("cp.async.wait_group %0;" :: "n"(n) : "memory")

// =============================================================================
// kA: forward split-K partials of i = x @ W^T via HMMA + cp.async double buffer.
// grid (16, KSPL), 256 thr (8 warps). CTA: p-tile 128, K range 128 (4 x 32).
// W fp32 chunks prefetched 2-deep; converted to 3 bf16 splits per chunk.
// Warp tile: 32b x 16p. smem 76.3 KB -> 2 CTAs/SM, 256 CTAs = single wave.
// =============================================================================
#define KA_RAWS   36                              // raw fp32 row stride (pad)
#define KA_RAWB   (128 * KA_RAWS * 4)             // 18432 B per buffer
#define KA_WS_OFF (2 * KA_RAWB)                   // 36864
#define KA_WSS    40                              // bf16 split-tile stride
#define KA_WSB    (128 * KA_WSS * 2)              // 10240 B per split
#define KA_XS_OFF (KA_WS_OFF + 3 * KA_WSB)        // 67584
#define KA_XSS    136                             // x tile stride (bf16)
#define KA_SMEM   (KA_XS_OFF + 32 * KA_XSS * 2)   // 76288 B

__global__ __launch_bounds__(256, 2) void kA(const float* __restrict__ x,
                                             const float* __restrict__ W) {
    extern __shared__ char sm[];
    __nv_bfloat16* Ws = reinterpret_cast<__nv_bfloat16*>(sm + KA_WS_OFF);
    __nv_bfloat16* xs = reinterpret_cast<__nv_bfloat16*>(sm + KA_XS_OFF);
    const u32 sbase = smem_u32(sm);

    const int tid = threadIdx.x, wid = tid >> 5, lane = tid & 31;
    const int gid = lane >> 2, tig = lane & 3;
    const int p0 = blockIdx.x * 128;
    const int k0 = blockIdx.y * 128;

    // stage x tile [32 b][128 k] as bf16 once (exact: x in {0,1})
    {
        const int b = tid >> 3, seg = tid & 7;
        const float4* xr = reinterpret_cast<const float4*>(x + b * PRE_ + k0 + seg * 16);
#pragma unroll
        for (int t = 0; t < 4; ++t) {
            float4 v = xr[t];
            *reinterpret_cast<u32*>(&xs[b * KA_XSS + seg * 16 + t * 4]) =
                pack_bf2(__float2bfloat16(v.x), __float2bfloat16(v.y));
            *reinterpret_cast<u32*>(&xs[b * KA_XSS + seg * 16 + t * 4 + 2]) =
                pack_bf2(__float2bfloat16(v.z), __float2bfloat16(v.w));
        }
    }

    auto prefetch = [&](int c, int d) {
        const int kb = k0 + c * 32;
        const u32 dstb = sbase + d * KA_RAWB;
#pragma unroll
        for (int i = 0; i < 4; ++i) {
            int u = tid + i * 256;
            int row = u >> 3, g = u & 7;
            CP_ASYNC16(dstb + (u32)(row * KA_RAWS + g * 4) * 4,
                       W + (size_t)(p0 + row) * PRE_ + kb + g * 4);
        }
        CP_COMMIT();
    };
    prefetch(0, 0);
    prefetch(1, 1);

    float acc[2][2][4];
#pragma unroll
    for (int i = 0; i < 2; ++i)
#pragma unroll
        for (int j = 0; j < 2; ++j)
#pragma unroll
            for (int r = 0; r < 4; ++r) acc[i][j][r] = 0.0f;

#pragma unroll 1
    for (int c = 0; c < 4; ++c) {
        if (c == 3) { CP_WAIT(0); } else { CP_WAIT(1); }
        __syncthreads();
        // convert raw fp32 chunk -> 3 bf16 split tiles
        {
            const float* rb = reinterpret_cast<const float*>(sm + (c & 1) * KA_RAWB);
            const int row = tid >> 1, half = tid & 1;
            const float* rp = rb + row * KA_RAWS + half * 16;
#pragma unroll
            for (int j = 0; j < 8; ++j) {
                float va = rp[j * 2], vb = rp[j * 2 + 1];
                __nv_bfloat16 h0, m0, l0, h1, m1, l1;
                split3(va, h0, m0, l0);
                split3(vb, h1, m1, l1);
                const int kcol = half * 16 + j * 2;
                *reinterpret_cast<u32*>(&Ws[(0 * 128 + row) * KA_WSS + kcol]) = pack_bf2(h0, h1);
                *reinterpret_cast<u32*>(&Ws[(1 * 128 + row) * KA_WSS + kcol]) = pack_bf2(m0, m1);
                *reinterpret_cast<u32*>(&Ws[(2 * 128 + row) * KA_WSS + kcol]) = pack_bf2(l0, l1);
            }
        }
        __syncthreads();
        if (c + 2 < 4) prefetch(c + 2, c & 1);   // overlap next DRAM read with MMA

#pragma unroll
        for (int ks = 0; ks < 2; ++ks) {
            const int kc = ks * 16 + tig * 2;     // chunk-local k
            const int kx = c * 32 + kc;           // x-tile k
            u32 a[2][4];
#pragma unroll
            for (int mf = 0; mf < 2; ++mf) {
                const int r0 = mf * 16 + gid;
                a[mf][0] = *reinterpret_cast<const u32*>(&xs[r0 * KA_XSS + kx]);
                a[mf][1] = *reinterpret_cast<const u32*>(&xs[(r0 + 8) * KA_XSS + kx]);
                a[mf][2] = *reinterpret_cast<const u32*>(&xs[r0 * KA_XSS + kx + 8]);
                a[mf][3] = *reinterpret_cast<const u32*>(&xs[(r0 + 8) * KA_XSS + kx + 8]);
            }
#pragma unroll
            for (int s = 0; s < 3; ++s)
#pragma unroll
                for (int nf = 0; nf < 2; ++nf) {
                    const int n = wid * 16 + nf * 8 + gid;
                    u32 b[2];
                    b[0] = *reinterpret_cast<const u32*>(&Ws[(s * 128 + n) * KA_WSS + kc]);
                    b[1] = *reinterpret_cast<const u32*>(&Ws[(s * 128 + n) * KA_WSS + kc + 8]);
                    mma16816(acc[0][nf], a[0], b);
                    mma16816(acc[1][nf], a[1], b);
                }
        }
        __syncthreads();
    }
    // epilogue: partials g_part[split][b][p]
    float* pp = g_part + (size_t)blockIdx.y * (B_ * POST_);
#pragma unroll
    for (int mf = 0; mf < 2; ++mf)
#pragma unroll
        for (int nf = 0; nf < 2; ++nf) {
            const int p = p0 + wid * 16 + nf * 8 + tig * 2;
            const int b = mf * 16 + gid;
            *reinterpret_cast<float2*>(&pp[(size_t)b * POST_ + p]) =
                make_float2(acc[mf][nf][0], acc[mf][nf][1]);
            *reinterpret_cast<float2*>(&pp[(size_t)(b + 8) * POST_ + p]) =
                make_float2(acc[mf][nf][2], acc[mf][nf][3]);
        }
}

// =============================================================================
// kBP: fused reduce + spike + traces + operand packing (no global trace bufs).
// grid 32 blocks x 256 thr; block handles 64 columns of both packs.
//  A[p][kk]: 0-31 & 32-63 = spike ; 64-95 = hi(tqn) ; 96-127 = lo(tqn)
//  B[q][kk]: 0-31 = hi(tp) ; 32-63 = lo(tp) ; 64-95 & 96-127 = x
// =============================================================================
__global__ __launch_bounds__(256) void kBP(const float* __restrict__ x,
                                           const float* __restrict__ tpre,
                                           const float* __restrict__ tpost,
                                           float* __restrict__ out_spike) {
    __shared__ float sp[32][68], tq[32][68], tp[32][68], xsm[32][68];
    const int tid = threadIdx.x;
    const int c0 = blockIdx.x * 64;

#pragma unroll
    for (int r = 0; r < 8; ++r) {
        int u = tid + r * 256;
        int b = u >> 6, j = u & 63;
        int gi = b * 2048 + c0 + j;
        float s = 0.0f;
#pragma unroll
        for (int k = 0; k < KSPL; ++k) s += g_part[(size_t)k * (B_ * POST_) + gi];
        float spike = (s >= 1.0f) ? 1.0f : 0.0f;
        out_spike[gi] = spike;
        sp[b][j] = spike;
        tq[b][j] = -(0.5f * tpost[gi] + spike);
        float xv = x[gi];
        xsm[b][j] = xv;
        tp[b][j]  = 0.5f * tpre[gi] + xv;
    }
    __syncthreads();

#pragma unroll
    for (int r = 0; r < 8; ++r) {
        int u = tid + r * 256;
        int rr = u >> 5, c4 = u & 31;
        int reg = c4 >> 3, bs = (c4 & 7) * 4;
        BV4 oA, oB;
#pragma unroll
        for (int t = 0; t < 4; ++t) {
            int b = bs + t;
            if (reg < 2) oA.v[t] = __float2bfloat16(sp[b][rr]);
            else {
                float v = tq[b][rr];
                __nv_bfloat16 h = __float2bfloat16(v);
                oA.v[t] = (reg == 2) ? h : __float2bfloat16(v - __bfloat162float(h));
            }
            if (reg >= 2) oB.v[t] = __float2bfloat16(xsm[b][rr]);
            else {
                float v = tp[b][rr];
                __nv_bfloat16 h = __float2bfloat16(v);
                oB.v[t] = (reg == 0) ? h : __float2bfloat16(v - __bfloat162float(h));
            }
        }
        *reinterpret_cast<BV4*>(&g_Apack[(size_t)(c0 + rr) * 128 + c4 * 4]) = oA;
        *reinterpret_cast<BV4*>(&g_Bpack[(size_t)(c0 + rr) * 128 + c4 * 4]) = oB;
    }
}

// =============================================================================
// kC: dw = clip(W) * (Apack @ Bpack^T), K=128 HMMA.
// grid (32, 16) = 512 CTAs, 256 thr. Tile 64p x 128q; warps 2(p) x 4(q).
// W tile prefetched via cp.async group 2 and consumed AFTER the MMA loop,
// hiding the DRAM latency. smem 86 KB -> 2 CTAs/SM.
// =============================================================================
#define KC_AS   136                         // pack tile stride (bf16)
#define KC_AB   (64 * KC_AS * 2)            // 17408
#define KC_BB   (128 * KC_AS * 2)           // 34816
#define KC_WS   132                         // W tile stride (fp32)
#define KC_WB   (64 * KC_WS * 4)            // 33792
#define KC_SMEM (KC_AB + KC_BB + KC_WB)     // 86016

__global__ __launch_bounds__(256, 2) void kC(const float* __restrict__ W,
                                             float* __restrict__ dw) {
    extern __shared__ char smc[];
    __nv_bfloat16* As = reinterpret_cast<__nv_bfloat16*>(smc);
    __nv_bfloat16* Bs = reinterpret_cast<__nv_bfloat16*>(smc + KC_AB);
    float* Wsm = reinterpret_cast<float*>(smc + KC_AB + KC_BB);
    const u32 sb = smem_u32(smc);

    const int tid = threadIdx.x, wid = tid >> 5, lane = tid & 31;
    const int gid = lane >> 2, tig = lane & 3;
    const int pw = wid >> 2, qw = wid & 3;
    const int p0 = blockIdx.x * 64, q0 = blockIdx.y * 128;

    // group 1: operand packs
#pragma unroll
    for (int i = 0; i < 4; ++i) {
        int u = tid + i * 256;
        int row = u >> 4, g = u & 15;
        CP_ASYNC16(sb + (u32)(row * KC_AS * 2 + g * 16),
                   g_Apack + (size_t)(p0 + row) * 128 + g * 8);
    }
#pragma unroll
    for (int i = 0; i < 8; ++i) {
        int u = tid + i * 256;
        int row = u >> 4, g = u & 15;
        CP_ASYNC16(sb + KC_AB + (u32)(row * KC_AS * 2 + g * 16),
                   g_Bpack + (size_t)(q0 + row) * 128 + g * 8);
    }
    CP_COMMIT();
    // group 2: W tile (consumed after MMA -> latency hidden)
#pragma unroll
    for (int i = 0; i < 8; ++i) {
        int u = tid + i * 256;
        int row = u >> 5, g = u & 31;
        CP_ASYNC16(sb + KC_AB + KC_BB + (u32)(row * KC_WS + g * 4) * 4,
                   W + (size_t)(p0 + row) * PRE_ + q0 + g * 4);
    }
    CP_COMMIT();

    CP_WAIT(1);          // packs ready (W may still be in flight)
    __syncthreads();

    float acc[2][4][4];
#pragma unroll
    for (int i = 0; i < 2; ++i)
#pragma unroll
        for (int j = 0; j < 4; ++j)
#pragma unroll
            for (int r = 0; r < 4; ++r) acc[i][j][r] = 0.0f;

#pragma unroll
    for (int kk = 0; kk < 8; ++kk) {
        const int kc = kk * 16 + tig * 2;
        u32 a[2][4];
#pragma unroll
        for (int mf = 0; mf < 2; ++mf) {
            const int r0 = pw * 32 + mf * 16 + gid;
            a[mf][0] = *reinterpret_cast<const u32*>(&As[r0 * KC_AS + kc]);
            a[mf][1] = *reinterpret_cast<const u32*>(&As[(r0 + 8) * KC_AS + kc]);
            a[mf][2] = *reinterpret_cast<const u32*>(&As[r0 * KC_AS + kc + 8]);
            a[mf][3] = *reinterpret_cast<const u32*>(&As[(r0 + 8) * KC_AS + kc + 8]);
        }
#pragma unroll
        for (int nf = 0; nf < 4; ++nf) {
            const int n = qw * 32 + nf * 8 + gid;
            u32 b[2];
            b[0] = *reinterpret_cast<const u32*>(&Bs[n * KC_AS + kc]);
            b[1] = *reinterpret_cast<const u32*>(&Bs[n * KC_AS + kc + 8]);
            mma16816(acc[0][nf], a[0], b);
            mma16816(acc[1][nf], a[1], b);
        }
    }

    CP_WAIT(0);          // W tile landed (overlapped with MMA above)
    __syncthreads();

#pragma unroll
    for (int mf = 0; mf < 2; ++mf)
#pragma unroll
        for (int nf = 0; nf < 4; ++nf) {
            const int pl = pw * 32 + mf * 16 + gid;
            const int ql = qw * 32 + nf * 8 + tig * 2;
            float2 w0 = *reinterpret_cast<const float2*>(&Wsm[pl * KC_WS + ql]);
            float2 w1 = *reinterpret_cast<const float2*>(&Wsm[(pl + 8) * KC_WS + ql]);
            float2 o0, o1;
            o0.x = fminf(fmaxf(w0.x, -1.f), 1.f) * acc[mf][nf][0];
            o0.y = fminf(fmaxf(w0.y, -1.f), 1.f) * acc[mf][nf][1];
            o1.x = fminf(fmaxf(w1.x, -1.f), 1.f) * acc[mf][nf][2];
            o1.y = fminf(fmaxf(w1.y, -1.f), 1.f) * acc[mf][nf][3];
            *reinterpret_cast<float2*>(&dw[(size_t)(p0 + pl) * PRE_ + q0 + ql]) = o0;
            *reinterpret_cast<float2*>(&dw[(size_t)(p0 + pl + 8) * PRE_ + q0 + ql]) = o1;
        }
}

// =============================================================================
extern "C" void kernel_launch(void* const* d_in, const int* in_sizes, int n_in,
                              void* d_out, int out_size) {
    const float* x     = (const float*)d_in[0];   // [32, 2048]
    const float* W     = (const float*)d_in[1];   // [2048, 2048]
    const float* tpre  = (const float*)d_in[2];   // [32, 2048]
    const float* tpost = (const float*)d_in[3];   // [32, 2048]
    float* out     = (float*)d_out;
    float* spike_o = out;                         // [32, 2048]
    float* dw_o    = out + B_ * POST_;            // [2048, 2048]

    cudaFuncSetAttribute(kA, cudaFuncAttributeMaxDynamicSharedMemorySize, KA_SMEM);
    cudaFuncSetAttribute(kC, cudaFuncAttributeMaxDynamicSharedMemorySize, KC_SMEM);

    kA<<<dim3(POST_ / 128, KSPL), 256, KA_SMEM>>>(x, W);
    kBP<<<32, 256>>>(x, tpre, tpost, spike_o);
    kC<<<dim3(POST_ / 64, PRE_ / 128), 256, KC_SMEM>>>(W, dw_o);
}

// round 12
// speedup vs baseline: 1.2726x; 1.2726x over previous
#include <cuda_runtime.h>
#include <cuda_bf16.h>

#define B_    32
#define PRE_  2048
#define POST_ 2048
#define KSPL  16

typedef unsigned int u32;

// ---- static device scratch ---------------------------------------------------
__device__ float g_part[KSPL * B_ * POST_];                   // fwd split-K partials
__device__ __align__(16) __nv_bfloat16 g_Apack[POST_ * 128];  // dw A operand (K-major)
__device__ __align__(16) __nv_bfloat16 g_Bpack[PRE_  * 128];  // dw B operand (K-major)

struct alignas(8) BV4 { __nv_bfloat16 v[4]; };

// ---- helpers -----------------------------------------------------------------
__device__ __forceinline__ u32 smem_u32(const void* p) {
    u32 a;
    asm("{ .reg .u64 t; cvta.to.shared.u64 t, %1; cvt.u32.u64 %0, t; }" : "=r"(a) : "l"(p));
    return a;
}
__device__ __forceinline__ void mma16816(float* d, const u32* a, const u32* b) {
    asm volatile(
        "mma.sync.aligned.m16n8k16.row.col.f32.bf16.bf16.f32 "
        "{%0,%1,%2,%3}, {%4,%5,%6,%7}, {%8,%9}, {%0,%1,%2,%3};"
        : "+f"(d[0]), "+f"(d[1]), "+f"(d[2]), "+f"(d[3])
        : "r"(a[0]), "r"(a[1]), "r"(a[2]), "r"(a[3]), "r"(b[0]), "r"(b[1]));
}
__device__ __forceinline__ void mma1688tf32(float* d, const u32* a, u32 b0, u32 b1) {
    asm volatile(
        "mma.sync.aligned.m16n8k8.row.col.f32.tf32.tf32.f32 "
        "{%0,%1,%2,%3}, {%4,%5,%6,%7}, {%8,%9}, {%0,%1,%2,%3};"
        : "+f"(d[0]), "+f"(d[1]), "+f"(d[2]), "+f"(d[3])
        : "r"(a[0]), "r"(a[1]), "r"(a[2]), "r"(a[3]), "r"(b0), "r"(b1));
}
__device__ __forceinline__ u32 cvt_tf32(float v) {
    u32 r;
    asm("cvt.rna.tf32.f32 %0, %1;" : "=r"(r) : "f"(v));
    return r;
}
__device__ __forceinline__ u32 pack_bf2(__nv_bfloat16 a, __nv_bfloat16 b) {
    __nv_bfloat162 t = __halves2bfloat162(a, b);
    return *reinterpret_cast<u32*>(&t);
}
#define CP_ASYNC16(dst, src) \
    asm volatile("cp.async.cg.shared.global [%0], [%1], 16;" :: "r"(dst), "l"(src) : "memory")
#define CP_COMMIT()  asm volatile("cp.async.commit_group;" ::: "memory")
#define CP_WAIT(n)   asm volatile("cp.async.wait_group %0;" :: "n"(n) : "memory")

// =============================================================================
// kA: forward split-K partials of i = x @ W^T via tf32 HMMA, 2-split W in regs.
// grid (POST/64 = 32, KSPL), 256 thr (8 warps). CTA: p-tile 64, K range 128
// (4 chunks of 32, cp.async double-buffered raw fp32 W). Warp: 32b x 8p.
// No smem convert phase: W hi/lo tf32 produced in registers at the MMA.
// smem ~35 KB, <=64 regs -> 4 CTAs/SM, 512 CTAs = single wave.
// =============================================================================
#define KA_RAWS 36                      // raw fp32 row stride (bank-spread pad)
#define KA_XSS  132                     // x tf32 row stride (u32)

__global__ __launch_bounds__(256, 4) void kA(const float* __restrict__ x,
                                             const float* __restrict__ W) {
    __shared__ float raw[2][64 * KA_RAWS];   // 18432 B
    __shared__ u32   xs[32 * KA_XSS];        // 16896 B

    const int tid = threadIdx.x, wid = tid >> 5, lane = tid & 31;
    const int gid = lane >> 2, tig = lane & 3;
    const int p0 = blockIdx.x * 64;
    const int k0 = blockIdx.y * 128;
    const u32 rawb = smem_u32(&raw[0][0]);

    // stage x tile [32 b][128 k] as exact tf32 once
    {
        const int b = tid >> 3, seg = tid & 7;
        const float4* xr = reinterpret_cast<const float4*>(x + b * PRE_ + k0 + seg * 16);
#pragma unroll
        for (int t = 0; t < 4; ++t) {
            float4 v = xr[t];
            xs[b * KA_XSS + seg * 16 + t * 4 + 0] = cvt_tf32(v.x);
            xs[b * KA_XSS + seg * 16 + t * 4 + 1] = cvt_tf32(v.y);
            xs[b * KA_XSS + seg * 16 + t * 4 + 2] = cvt_tf32(v.z);
            xs[b * KA_XSS + seg * 16 + t * 4 + 3] = cvt_tf32(v.w);
        }
    }

    auto prefetch = [&](int c, int d) {
        const int kb = k0 + c * 32;
#pragma unroll
        for (int i = 0; i < 2; ++i) {
            int u = tid + i * 256;
            int row = u >> 3, g = u & 7;
            CP_ASYNC16(rawb + (u32)(d * 64 * KA_RAWS + row * KA_RAWS + g * 4) * 4,
                       W + (size_t)(p0 + row) * PRE_ + kb + g * 4);
        }
        CP_COMMIT();
    };
    prefetch(0, 0);
    prefetch(1, 1);

    float acc[2][4];
#pragma unroll
    for (int i = 0; i < 2; ++i)
#pragma unroll
        for (int r = 0; r < 4; ++r) acc[i][r] = 0.0f;

    const int n = wid * 8 + gid;          // warp's p row for B fragments

#pragma unroll 1
    for (int c = 0; c < 4; ++c) {
        if (c == 3) { CP_WAIT(0); } else { CP_WAIT(1); }
        __syncthreads();
        const float* rb = &raw[c & 1][0];
#pragma unroll
        for (int ks = 0; ks < 4; ++ks) {
            const int kc = ks * 8;
            const int kx = c * 32 + kc;
            // A fragments (x, exact tf32)
            u32 a[2][4];
#pragma unroll
            for (int mf = 0; mf < 2; ++mf) {
                const int r0 = mf * 16 + gid;
                a[mf][0] = xs[r0 * KA_XSS + kx + tig];
                a[mf][1] = xs[(r0 + 8) * KA_XSS + kx + tig];
                a[mf][2] = xs[r0 * KA_XSS + kx + tig + 4];
                a[mf][3] = xs[(r0 + 8) * KA_XSS + kx + tig + 4];
            }
            // B fragments: fp32 -> (hi, lo) tf32 in registers
            float w0 = rb[n * KA_RAWS + kc + tig];
            float w1 = rb[n * KA_RAWS + kc + tig + 4];
            u32 h0 = cvt_tf32(w0), h1 = cvt_tf32(w1);
            u32 l0 = cvt_tf32(w0 - __uint_as_float(h0));
            u32 l1 = cvt_tf32(w1 - __uint_as_float(h1));
            mma1688tf32(acc[0], a[0], h0, h1);
            mma1688tf32(acc[1], a[1], h0, h1);
            mma1688tf32(acc[0], a[0], l0, l1);
            mma1688tf32(acc[1], a[1], l0, l1);
        }
        __syncthreads();
        if (c + 2 < 4) prefetch(c + 2, c & 1);
    }

    // epilogue: partials g_part[split][b][p]
    float* pp = g_part + (size_t)blockIdx.y * (B_ * POST_);
    const int p = p0 + wid * 8 + tig * 2;
#pragma unroll
    for (int mf = 0; mf < 2; ++mf) {
        const int b = mf * 16 + gid;
        *reinterpret_cast<float2*>(&pp[(size_t)b * POST_ + p]) =
            make_float2(acc[mf][0], acc[mf][1]);
        *reinterpret_cast<float2*>(&pp[(size_t)(b + 8) * POST_ + p]) =
            make_float2(acc[mf][2], acc[mf][3]);
    }
}

// =============================================================================
// kBP: fused reduce + spike + traces + operand packing. grid 64 x 256 thr,
// 32 columns of both packs per block.
//  A[p][kk]: 0-31 & 32-63 = spike ; 64-95 = hi(tqn) ; 96-127 = lo(tqn)
//  B[q][kk]: 0-31 = hi(tp) ; 32-63 = lo(tp) ; 64-95 & 96-127 = x
// =============================================================================
__global__ __launch_bounds__(256) void kBP(const float* __restrict__ x,
                                           const float* __restrict__ tpre,
                                           const float* __restrict__ tpost,
                                           float* __restrict__ out_spike) {
    __shared__ float sp[32][36], tq[32][36], tp[32][36], xsm[32][36];
    const int tid = threadIdx.x;
    const int c0 = blockIdx.x * 32;

#pragma unroll
    for (int r = 0; r < 4; ++r) {
        int u = tid + r * 256;
        int b = u >> 5, j = u & 31;
        int gi = b * 2048 + c0 + j;
        float s = 0.0f;
#pragma unroll
        for (int k = 0; k < KSPL; ++k) s += g_part[(size_t)k * (B_ * POST_) + gi];
        float spike = (s >= 1.0f) ? 1.0f : 0.0f;
        out_spike[gi] = spike;
        sp[b][j] = spike;
        tq[b][j] = -(0.5f * tpost[gi] + spike);
        float xv = x[gi];
        xsm[b][j] = xv;
        tp[b][j]  = 0.5f * tpre[gi] + xv;
    }
    __syncthreads();

#pragma unroll
    for (int r = 0; r < 4; ++r) {
        int u = tid + r * 256;
        int rr = u >> 5, c4 = u & 31;
        int reg = c4 >> 3, bs = (c4 & 7) * 4;
        BV4 oA, oB;
#pragma unroll
        for (int t = 0; t < 4; ++t) {
            int b = bs + t;
            if (reg < 2) oA.v[t] = __float2bfloat16(sp[b][rr]);
            else {
                float v = tq[b][rr];
                __nv_bfloat16 h = __float2bfloat16(v);
                oA.v[t] = (reg == 2) ? h : __float2bfloat16(v - __bfloat162float(h));
            }
            if (reg >= 2) oB.v[t] = __float2bfloat16(xsm[b][rr]);
            else {
                float v = tp[b][rr];
                __nv_bfloat16 h = __float2bfloat16(v);
                oB.v[t] = (reg == 0) ? h : __float2bfloat16(v - __bfloat162float(h));
            }
        }
        *reinterpret_cast<BV4*>(&g_Apack[(size_t)(c0 + rr) * 128 + c4 * 4]) = oA;
        *reinterpret_cast<BV4*>(&g_Bpack[(size_t)(c0 + rr) * 128 + c4 * 4]) = oB;
    }
}

// =============================================================================
// kC: dw = clip(W) * (Apack @ Bpack^T), K=128 bf16 HMMA.
// grid (32, 16) = 512 CTAs, 256 thr. Tile 64p x 128q; warps 2(p) x 4(q).
// W tile prefetched via cp.async group 2, consumed after the MMA loop.
// =============================================================================
#define KC_AS   136                         // pack tile stride (bf16)
#define KC_AB   (64 * KC_AS * 2)            // 17408
#define KC_BB   (128 * KC_AS * 2)           // 34816
#define KC_WS   132                         // W tile stride (fp32)
#define KC_WB   (64 * KC_WS * 4)            // 33792
#define KC_SMEM (KC_AB + KC_BB + KC_WB)     // 86016

__global__ __launch_bounds__(256, 2) void kC(const float* __restrict__ W,
                                             float* __restrict__ dw) {
    extern __shared__ char smc[];
    __nv_bfloat16* As = reinterpret_cast<__nv_bfloat16*>(smc);
    __nv_bfloat16* Bs = reinterpret_cast<__nv_bfloat16*>(smc + KC_AB);
    float* Wsm = reinterpret_cast<float*>(smc + KC_AB + KC_BB);
    const u32 sb = smem_u32(smc);

    const int tid = threadIdx.x, wid = tid >> 5, lane = tid & 31;
    const int gid = lane >> 2, tig = lane & 3;
    const int pw = wid >> 2, qw = wid & 3;
    const int p0 = blockIdx.x * 64, q0 = blockIdx.y * 128;

    // group 1: operand packs
#pragma unroll
    for (int i = 0; i < 4; ++i) {
        int u = tid + i * 256;
        int row = u >> 4, g = u & 15;
        CP_ASYNC16(sb + (u32)(row * KC_AS * 2 + g * 16),
                   g_Apack + (size_t)(p0 + row) * 128 + g * 8);
    }
#pragma unroll
    for (int i = 0; i < 8; ++i) {
        int u = tid + i * 256;
        int row = u >> 4, g = u & 15;
        CP_ASYNC16(sb + KC_AB + (u32)(row * KC_AS * 2 + g * 16),
                   g_Bpack + (size_t)(q0 + row) * 128 + g * 8);
    }
    CP_COMMIT();
    // group 2: W tile (consumed after MMA -> latency hidden)
#pragma unroll
    for (int i = 0; i < 8; ++i) {
        int u = tid + i * 256;
        int row = u >> 5, g = u & 31;
        CP_ASYNC16(sb + KC_AB + KC_BB + (u32)(row * KC_WS + g * 4) * 4,
                   W + (size_t)(p0 + row) * PRE_ + q0 + g * 4);
    }
    CP_COMMIT();

    CP_WAIT(1);          // packs ready (W may still be in flight)
    __syncthreads();

    float acc[2][4][4];
#pragma unroll
    for (int i = 0; i < 2; ++i)
#pragma unroll
        for (int j = 0; j < 4; ++j)
#pragma unroll
            for (int r = 0; r < 4; ++r) acc[i][j][r] = 0.0f;

#pragma unroll
    for (int kk = 0; kk < 8; ++kk) {
        const int kc = kk * 16 + tig * 2;
        u32 a[2][4];
#pragma unroll
        for (int mf = 0; mf < 2; ++mf) {
            const int r0 = pw * 32 + mf * 16 + gid;
            a[mf][0] = *reinterpret_cast<const u32*>(&As[r0 * KC_AS + kc]);
            a[mf][1] = *reinterpret_cast<const u32*>(&As[(r0 + 8) * KC_AS + kc]);
            a[mf][2] = *reinterpret_cast<const u32*>(&As[r0 * KC_AS + kc + 8]);
            a[mf][3] = *reinterpret_cast<const u32*>(&As[(r0 + 8) * KC_AS + kc + 8]);
        }
#pragma unroll
        for (int nf = 0; nf < 4; ++nf) {
            const int n = qw * 32 + nf * 8 + gid;
            u32 b[2];
            b[0] = *reinterpret_cast<const u32*>(&Bs[n * KC_AS + kc]);
            b[1] = *reinterpret_cast<const u32*>(&Bs[n * KC_AS + kc + 8]);
            mma16816(acc[0][nf], a[0], b);
            mma16816(acc[1][nf], a[1], b);
        }
    }

    CP_WAIT(0);          // W tile landed (overlapped with MMA above)
    __syncthreads();

#pragma unroll
    for (int mf = 0; mf < 2; ++mf)
#pragma unroll
        for (int nf = 0; nf < 4; ++nf) {
            const int pl = pw * 32 + mf * 16 + gid;
            const int ql = qw * 32 + nf * 8 + tig * 2;
            float2 w0 = *reinterpret_cast<const float2*>(&Wsm[pl * KC_WS + ql]);
            float2 w1 = *reinterpret_cast<const float2*>(&Wsm[(pl + 8) * KC_WS + ql]);
            float2 o0, o1;
            o0.x = fminf(fmaxf(w0.x, -1.f), 1.f) * acc[mf][nf][0];
            o0.y = fminf(fmaxf(w0.y, -1.f), 1.f) * acc[mf][nf][1];
            o1.x = fminf(fmaxf(w1.x, -1.f), 1.f) * acc[mf][nf][2];
            o1.y = fminf(fmaxf(w1.y, -1.f), 1.f) * acc[mf][nf][3];
            *reinterpret_cast<float2*>(&dw[(size_t)(p0 + pl) * PRE_ + q0 + ql]) = o0;
            *reinterpret_cast<float2*>(&dw[(size_t)(p0 + pl + 8) * PRE_ + q0 + ql]) = o1;
        }
}

// =============================================================================
extern "C" void kernel_launch(void* const* d_in, const int* in_sizes, int n_in,
                              void* d_out, int out_size) {
    const float* x     = (const float*)d_in[0];   // [32, 2048]
    const float* W     = (const float*)d_in[1];   // [2048, 2048]
    const float* tpre  = (const float*)d_in[2];   // [32, 2048]
    const float* tpost = (const float*)d_in[3];   // [32, 2048]
    float* out     = (float*)d_out;
    float* spike_o = out;                         // [32, 2048]
    float* dw_o    = out + B_ * POST_;            // [2048, 2048]

    cudaFuncSetAttribute(kC, cudaFuncAttributeMaxDynamicSharedMemorySize, KC_SMEM);

    kA<<<dim3(POST_ / 64, KSPL), 256>>>(x, W);
    kBP<<<64, 256>>>(x, tpre, tpost, spike_o);
    kC<<<dim3(POST_ / 64, PRE_ / 128), 256, KC_SMEM>>>(W, dw_o);
}